// round 6
// baseline (speedup 1.0000x reference)
#include <cuda_runtime.h>
#include <math.h>

#define NB 4
#define NS 256
#define ND 300
#define NM (NB*NS)   // 1024 rows
#define NK 300
#define N3 (3*ND)    // 900: pd | ph | g1(+b_f)
#define CC 5.0f
#define IG 2

// weight: exp(C*tanh(x/C)) = e^C * 2^(K2/(1 + 2^(x*K_PRE))); e^C cancels in softmax
#define K_PRE 0.5770780163555854f     //  2*log2(e)/C
#define K2   -14.426950408889634f     // -2*C*log2(e)
#define LOG2E 1.4426950408889634f

// Scratch (static device globals — no allocation allowed)
__device__ float g_rep[NM*ND];
__device__ float g_dhg[NM*N3];
__device__ float g_attn[NM*ND];
__device__ float g_p0[NM*ND];
__device__ float g_p1[NM*ND];
__device__ float g_p2[NM*ND];
__device__ float g_p3[NM*ND];
__device__ float g_p4[NM*ND];
__device__ float g_p5[NM*ND];

#define BM 64
#define BN 64
#define BK 20
#define LPT 5        // loads/thread/tile: 64*20/256

typedef unsigned long long ull;

// ---------------- packed f32x2 helpers (FFMA2: 2x fp32 FMA rate) ------------
__device__ __forceinline__ ull pack2(float x, float y){
    ull r; asm("mov.b64 %0, {%1,%2};" : "=l"(r) : "f"(x), "f"(y)); return r;
}
__device__ __forceinline__ void ffma2(ull& d, ull a, ull b){
    asm("fma.rn.f32x2 %0, %1, %2, %0;" : "+l"(d) : "l"(a), "l"(b));
}
__device__ __forceinline__ float2 unpk(ull v){
    float2 r; asm("mov.b64 {%0,%1}, %2;" : "=f"(r.x), "=f"(r.y) : "l"(v)); return r;
}
__device__ __forceinline__ float ex2a(float x){ float y; asm("ex2.approx.f32 %0,%1;" : "=f"(y):"f"(x)); return y; }
__device__ __forceinline__ float rcpa(float x){ float y; asm("rcp.approx.f32 %0,%1;" : "=f"(y):"f"(x)); return y; }

// weight from precomputed pd=2^(dep'), ph=2^(head'): 4 instr, 2 MUFU
__device__ __forceinline__ float wfun2(float pd, float ph)
{
    float r = rcpa(fmaf(pd, ph, 1.f));
    return ex2a(K2 * r);
}

// 64x64 tile GEMM, C[m,n] += A[m,k]*W[n,k]. Double-buffered smem.
__device__ __forceinline__ void gemm_core(const float* __restrict__ A,
                                          const float* __restrict__ W,
                                          int m0, int n0, int kstart, int niter,
                                          ull (&acc)[4][2])
{
    __shared__ __align__(16) float As[2][BK][BM+4];
    __shared__ __align__(16) float Bs[2][BK][BN+4];
    const int tid = threadIdx.x;
    const int tx = tid & 15, ty = tid >> 4;

    #pragma unroll
    for (int e = 0; e < LPT; ++e) {
        int idx = tid + e*256;
        int r = idx / BK, c = idx - r*BK;
        As[0][c][r] = A[(m0 + r)*NK + kstart + c];
        int gn = n0 + r;
        Bs[0][c][r] = (gn < ND) ? W[gn*NK + kstart + c] : 0.f;
    }
    __syncthreads();

    int buf = 0;
    for (int it = 0; it < niter; ++it) {
        const bool has_next = (it + 1 < niter);
        float ra[LPT], rb[LPT];
        if (has_next) {
            int kn = kstart + (it + 1)*BK;
            #pragma unroll
            for (int e = 0; e < LPT; ++e) {
                int idx = tid + e*256;
                int r = idx / BK, c = idx - r*BK;
                ra[e] = A[(m0 + r)*NK + kn + c];
                int gn = n0 + r;
                rb[e] = (gn < ND) ? W[gn*NK + kn + c] : 0.f;
            }
        }
        #pragma unroll
        for (int k = 0; k < BK; ++k) {
            const float4 af = *(const float4*)&As[buf][k][ty*4];
            const ull b0 = *(const ull*)&Bs[buf][k][tx*4];
            const ull b1 = *(const ull*)&Bs[buf][k][tx*4 + 2];
            ull a0 = pack2(af.x, af.x);
            ull a1 = pack2(af.y, af.y);
            ull a2 = pack2(af.z, af.z);
            ull a3 = pack2(af.w, af.w);
            ffma2(acc[0][0], a0, b0); ffma2(acc[0][1], a0, b1);
            ffma2(acc[1][0], a1, b0); ffma2(acc[1][1], a1, b1);
            ffma2(acc[2][0], a2, b0); ffma2(acc[2][1], a2, b1);
            ffma2(acc[3][0], a3, b0); ffma2(acc[3][1], a3, b1);
        }
        if (has_next) {
            __syncthreads();
            #pragma unroll
            for (int e = 0; e < LPT; ++e) {
                int idx = tid + e*256;
                int r = idx / BK, c = idx - r*BK;
                As[buf^1][c][r] = ra[e];
                Bs[buf^1][c][r] = rb[e];
            }
            __syncthreads();
            buf ^= 1;
        }
    }
}

__device__ __forceinline__ void store_partial(float* __restrict__ dst,
                                              ull (&acc)[4][2], int m0, int n0)
{
    const int tx = threadIdx.x & 15, ty = threadIdx.x >> 4;
    #pragma unroll
    for (int p = 0; p < 4; ++p) {
        int m = m0 + ty*4 + p;
        #pragma unroll
        for (int qq = 0; qq < 2; ++qq) {
            float2 v = unpk(acc[p][qq]);
            int n = n0 + tx*4 + qq*2;
            if (n < ND)     dst[m*ND + n]     = v.x;
            if (n + 1 < ND) dst[m*ND + n + 1] = v.y;
        }
    }
}

__device__ float* part_ptr(int z)
{
    switch (z) {
        case 0: return g_p0; case 1: return g_p1; case 2: return g_p2;
        case 3: return g_p3; case 4: return g_p4; default: return g_p5;
    }
}

// ---- P1: rep partial GEMM, split-K4 (z: k0=80z, iters {4,4,4,3}) -----------
__global__ void __launch_bounds__(256)
gemm_rep_split(const float* __restrict__ A, const float* __restrict__ W)
{
    const int m0 = blockIdx.y * BM, n0 = blockIdx.x * BN;
    const int z = blockIdx.z;
    ull acc[4][2] = {};
    gemm_core(A, W, m0, n0, z*80, (z == 3) ? 3 : 4, acc);
    store_partial(part_ptr(z), acc, m0, n0);
}

// ---- P1b: g_rep = elu(p0+p1+p2+p3 + b_fc) ----------------------------------
__global__ void __launch_bounds__(256)
finish_rep(const float* __restrict__ bias)
{
    int idx = blockIdx.x * 256 + threadIdx.x;
    if (idx >= NM*ND) return;
    int n = idx % ND;
    float v = (g_p0[idx] + g_p1[idx]) + (g_p2[idx] + g_p3[idx]) + bias[n];
    g_rep[idx] = (v > 0.f) ? v : expm1f(v);
}

// ---- P2: triple GEMM, split-K2 x 3 matrices (z = mat*2 + half) -------------
__global__ void __launch_bounds__(256)
gemm_triple_split(const float* __restrict__ W1, const float* __restrict__ W2,
                  const float* __restrict__ Wf1)
{
    const int m0 = blockIdx.y * BM, n0 = blockIdx.x * BN;
    const int z = blockIdx.z;
    const int mat = z >> 1, half = z & 1;
    const float* W = (mat == 0) ? W1 : ((mat == 1) ? W2 : Wf1);
    ull acc[4][2] = {};
    gemm_core(g_rep, W, m0, n0, half ? 160 : 0, half ? 7 : 8, acc);
    store_partial(part_ptr(z), acc, m0, n0);
}

// ---- P2b: combine triple partials; pd=2^(dep*K_PRE), ph=2^((head+b1)*K_PRE)
__global__ void __launch_bounds__(256)
finish_triple(const float* __restrict__ b1, const float* __restrict__ bf)
{
    int idx = blockIdx.x * 256 + threadIdx.x;
    if (idx >= NM*N3) return;
    int m = idx / N3, c = idx - m*N3;
    int z = c / ND, nn = c - z*ND;
    int e = m*ND + nn;
    float val;
    if (z == 0)      val = ex2a((g_p0[e] + g_p1[e]) * K_PRE);
    else if (z == 1) val = ex2a((g_p2[e] + g_p3[e] + b1[nn]) * K_PRE);
    else             val = g_p4[e] + g_p5[e] + bf[nn];
    g_dhg[idx] = val;
}

// ---- P3: attention (IG=2, compacted byte-offset list, j x4 unroll) ---------
__global__ void __launch_bounds__(320)
attn_kernel(const int* __restrict__ rmask)
{
    const int b = blockIdx.y;
    const int i0 = blockIdx.x * IG;
    const int t = threadIdx.x;

    __shared__ __align__(16) int2 joff[NS];   // (j*N3*4, j*ND*4) byte offsets
    __shared__ int wcnt[8];
    __shared__ int nvalid_s;
    __shared__ int jfirst_s;

    bool v = false;
    unsigned bal = 0;
    if (t < NS) {
        v = (t > i0) && (rmask[b*NS + t] != 0);
        bal = __ballot_sync(0xFFFFFFFFu, v);
        if ((t & 31) == 0) wcnt[t >> 5] = __popc(bal);
    }
    __syncthreads();
    if (t == 0) {
        int a = 0;
        #pragma unroll
        for (int k = 0; k < 8; ++k) { int c = wcnt[k]; wcnt[k] = a; a += c; }
        nvalid_s = a;
    }
    __syncthreads();
    if (t < NS && v) {
        int pos = wcnt[t >> 5] + __popc(bal & ((1u << (t & 31)) - 1u));
        joff[pos] = make_int2(t * (N3*4), t * (ND*4));
        if (pos == 0) jfirst_s = t;
    }
    __syncthreads();

    const int nvalid = nvalid_s;
    if (t >= ND) return;

    const float ph0 = g_dhg[(size_t)(b*NS + i0    )*N3 + ND + t];
    const float ph1 = g_dhg[(size_t)(b*NS + i0 + 1)*N3 + ND + t];
    const char* __restrict__ pdp = (const char*)(g_dhg + (size_t)(b*NS)*N3 + t);
    const char* __restrict__ rpp = (const char*)(g_rep + (size_t)(b*NS)*ND + t);

    float s0 = 0.f, w0 = 0.f, s1 = 0.f, w1 = 0.f;
    int idx = 0;
    for (; idx + 4 <= nvalid; idx += 4) {
        const int4 oa = *(const int4*)&joff[idx];      // j0: (x,y)  j1: (z,w)
        const int4 ob = *(const int4*)&joff[idx + 2];  // j2, j3
        float pda = *(const float*)(pdp + oa.x);
        float pdb = *(const float*)(pdp + oa.z);
        float pdc = *(const float*)(pdp + ob.x);
        float pdd = *(const float*)(pdp + ob.z);
        float rva = *(const float*)(rpp + oa.y);
        float rvb = *(const float*)(rpp + oa.w);
        float rvc = *(const float*)(rpp + ob.y);
        float rvd = *(const float*)(rpp + ob.w);
        float e0a = wfun2(pda, ph0), e1a = wfun2(pda, ph1);
        float e0b = wfun2(pdb, ph0), e1b = wfun2(pdb, ph1);
        float e0c = wfun2(pdc, ph0), e1c = wfun2(pdc, ph1);
        float e0d = wfun2(pdd, ph0), e1d = wfun2(pdd, ph1);
        s0 += (e0a + e0b) + (e0c + e0d);
        s1 += (e1a + e1b) + (e1c + e1d);
        w0 = fmaf(e0a, rva, fmaf(e0b, rvb, fmaf(e0c, rvc, fmaf(e0d, rvd, w0))));
        w1 = fmaf(e1a, rva, fmaf(e1b, rvb, fmaf(e1c, rvc, fmaf(e1d, rvd, w1))));
    }
    for (; idx < nvalid; ++idx) {
        const int2 o = joff[idx];
        float pd = *(const float*)(pdp + o.x);
        float rv = *(const float*)(rpp + o.y);
        float e0 = wfun2(pd, ph0), e1 = wfun2(pd, ph1);
        s0 += e0;  w0 = fmaf(e0, rv, w0);
        s1 += e1;  w1 = fmaf(e1, rv, w1);
    }
    // i1 = i0+1 must exclude j == i0+1 (only possibly-invalid entry = first)
    if (nvalid > 0 && jfirst_s == i0 + 1) {
        float pd = *(const float*)(pdp + (i0 + 1)*(N3*4));
        float rv = *(const float*)(rpp + (i0 + 1)*(ND*4));
        float e1 = wfun2(pd, ph1);
        s1 -= e1;  w1 = fmaf(-e1, rv, w1);
    }
    float d0 = s0 + ((s0 == 0.f) ? 1.f : 0.f) + 1e-20f;
    float d1 = s1 + ((s1 == 0.f) ? 1.f : 0.f) + 1e-20f;
    g_attn[(size_t)(b*NS + i0    )*ND + t] = __fdividef(w0, d0);
    g_attn[(size_t)(b*NS + i0 + 1)*ND + t] = __fdividef(w1, d1);
}

// ---- P4: attn @ W_f2^T, split-K4 partials ----------------------------------
__global__ void __launch_bounds__(256)
gemm_final_split(const float* __restrict__ Wf2)
{
    const int m0 = blockIdx.y * BM, n0 = blockIdx.x * BN;
    const int z = blockIdx.z;
    ull acc[4][2] = {};
    gemm_core(g_attn, Wf2, m0, n0, z*80, (z == 3) ? 3 : 4, acc);
    store_partial(part_ptr(z), acc, m0, n0);
}

// ---- P4b: gate + blend + mask ----------------------------------------------
__global__ void __launch_bounds__(256)
final_epi(const int* __restrict__ rmask, float* __restrict__ out)
{
    int idx = blockIdx.x * 256 + threadIdx.x;
    if (idx >= NM*ND) return;
    int m = idx / ND, n = idx - m*ND;
    float vv = (g_p0[idx] + g_p1[idx]) + (g_p2[idx] + g_p3[idx])
             + g_dhg[m*N3 + 2*ND + n];
    float gate = rcpa(1.f + ex2a(-vv * LOG2E));
    float r = g_rep[idx];
    float a = g_attn[idx];
    out[idx] = (gate*r + (1.f - gate)*a) * (float)rmask[m];
}

extern "C" void kernel_launch(void* const* d_in, const int* in_sizes, int n_in,
                              void* d_out, int out_size)
{
    const float* inputs = (const float*)d_in[0];
    const int*   rmask  = (const int*)d_in[1];
    const float* W_fc   = (const float*)d_in[2];
    const float* b_fc   = (const float*)d_in[3];
    const float* W1     = (const float*)d_in[4];
    const float* W2     = (const float*)d_in[5];
    const float* b1     = (const float*)d_in[6];
    const float* W_f1   = (const float*)d_in[7];
    const float* W_f2   = (const float*)d_in[8];
    const float* b_f    = (const float*)d_in[9];
    float* out = (float*)d_out;

    dim3 blk(256);
    const int eBlocks  = (NM*ND + 255) / 256;
    const int eBlocks3 = (NM*N3 + 255) / 256;

    gemm_rep_split   <<<dim3(5, 16, 4), blk>>>(inputs, W_fc);
    finish_rep       <<<eBlocks, blk>>>(b_fc);
    gemm_triple_split<<<dim3(5, 16, 6), blk>>>(W1, W2, W_f1);
    finish_triple    <<<eBlocks3, blk>>>(b1, b_f);
    attn_kernel      <<<dim3(NS/IG, NB), 320>>>(rmask);
    gemm_final_split <<<dim3(5, 16, 4), blk>>>(W_f2);
    final_epi        <<<eBlocks, blk>>>(rmask, out);
}